// round 13
// baseline (speedup 1.0000x reference)
#include <cuda_runtime.h>
#include <cuda_bf16.h>

// Problem constants
#define NSUB 3
#define M 4096
#define D 128
#define BTOT (NSUB*M)
#define TILE 128
#define NT (M/TILE)            // 32 block-rows per subset
#define NTRI (NT*(NT+1)/2)     // 528 upper-triangle tiles per subset
#define LDT 136                // bf16 smem tile leading dim (272B rows)
#define POS_CAP 128            // per-row positive-sim list capacity
#define NEG_CAP (1<<20)        // global spill list for negatives > 0.49

// Scratch (device globals -- no allocations allowed)
__device__ __nv_bfloat16 g_embB[BTOT * D];
__device__ int           g_tg[BTOT];
__device__ unsigned      g_mnE[BTOT];            // encoded row max_neg
__device__ int           g_pcnt[BTOT];           // positives count per row
__device__ float         g_pos[(size_t)BTOT * POS_CAP]; // 6.3 MB
__device__ int           g_ncnt;                 // spill count
__device__ int           g_negrow[NEG_CAP];
__device__ float         g_negval[NEG_CAP];
__device__ float         g_thrn[BTOT];
__device__ float         g_acc;
__device__ int           g_tmode;                // 0 = int32 targets, 1 = int64

// Monotone float <-> unsigned encoding (for atomicMax on float)
__device__ __forceinline__ unsigned encf(float f) {
    unsigned u = __float_as_uint(f);
    return (u & 0x80000000u) ? ~u : (u | 0x80000000u);
}
__device__ __forceinline__ float decf(unsigned e) {
    unsigned u = (e & 0x80000000u) ? (e & 0x7fffffffu) : ~e;
    return __uint_as_float(u);
}

__device__ __forceinline__ void push_pos(int row, float s) {
    int k = atomicAdd(&g_pcnt[row], 1);
    if (k < POS_CAP) g_pos[(size_t)row * POS_CAP + k] = s;
}
__device__ __forceinline__ void push_neg(int row, float s) {
    int k = atomicAdd(&g_ncnt, 1);
    if (k < NEG_CAP) { g_negrow[k] = row; g_negval[k] = s; }
}

// ---------------------------------------------------------------------------
// Detect target dtype layout (targets in [0,512): int64 layout => odd words 0)
// ---------------------------------------------------------------------------
__global__ void detect_kernel(const int* __restrict__ tgt32) {
    int odd_or = 0;
    #pragma unroll
    for (int k = 0; k < 64; k++) odd_or |= tgt32[2 * k + 1];
    g_tmode = (odd_or == 0) ? 1 : 0;
    g_acc = 0.0f;
    g_ncnt = 0;
}

// ---------------------------------------------------------------------------
// Prep: fp32 -> bf16 (vectorized), targets -> int32, reset per-row state
// ---------------------------------------------------------------------------
__global__ void prep_kernel(const float* __restrict__ emb,
                            const int* __restrict__ tgt32) {
    int idx = blockIdx.x * 256 + threadIdx.x;
    if (idx < BTOT * D / 4) {
        float4 v = reinterpret_cast<const float4*>(emb)[idx];
        __nv_bfloat162 a = __float22bfloat162_rn(make_float2(v.x, v.y));
        __nv_bfloat162 b = __float22bfloat162_rn(make_float2(v.z, v.w));
        uint2 pk;
        pk.x = *reinterpret_cast<unsigned*>(&a);
        pk.y = *reinterpret_cast<unsigned*>(&b);
        reinterpret_cast<uint2*>(g_embB)[idx] = pk;
    }
    if (idx < BTOT) {
        g_tg[idx] = g_tmode ? tgt32[2 * idx] : tgt32[idx];
        g_mnE[idx] = encf(-1e30f);
        g_pcnt[idx] = 0;
    }
}

// ---------------------------------------------------------------------------
// Single triangular GEMM pass with register-resident epilogue.
// Raw mma.sync.m16n8k16 (documented fragment layout):
//   lane = 4*g + tig;  g = lane>>2 (0..7), tig = lane&3 (0..3)
//   A(row-major m16 k16): a0=(g, 2tig+{0,1}) a1=(g+8, 2tig) a2=(g, 2tig+8) a3=(g+8, 2tig+8)
//   B(col-major k16 n8):  b0=(k=2tig+{0,1}, n=g) b1=(k=2tig+8+{0,1}, n=g)
//   C  f32:               c0,c1=(g, 2tig+{0,1}) c2,c3=(g+8, 2tig+{0,1})
// Warp w owns rows [w*16, w*16+16), all 128 cols (16 n8-tiles) -> 64 acc regs.
// Epilogue: classify each element once in registers; row maxima via 2 shfls,
// col maxima (off-diag) via 3 shfls + smem atomicMax staging + 1 flush.
// ---------------------------------------------------------------------------
__global__ __launch_bounds__(256, 2) void simpass_kernel() {
    extern __shared__ __nv_bfloat16 smem[];
    __nv_bfloat16* As = smem;                   // [128][LDT]
    __nv_bfloat16* Bs = smem + TILE * LDT;      // [128][LDT]

    __shared__ int srt[TILE];        // targets of br rows
    __shared__ int sct[TILE];        // targets of bc rows
    __shared__ unsigned colE[TILE];  // encoded col maxima (off-diag)

    const int subset = blockIdx.z;
    const int tid = threadIdx.x;

    // Decode upper-triangle tile index -> (br, bc)
    int rem = blockIdx.x, br = 0;
    while (rem >= NT - br) { rem -= NT - br; br++; }
    const int bc = br + rem;
    const int row0 = br * TILE;
    const int col0 = bc * TILE;
    const bool dg = (br == bc);

    const __nv_bfloat16* Eb = g_embB + (size_t)subset * M * D;

    if (tid < TILE) {
        srt[tid] = g_tg[subset * M + row0 + tid];
        colE[tid] = encf(-1e30f);
    } else {
        sct[tid - TILE] = g_tg[subset * M + col0 + (tid - TILE)];
    }

    // Cooperative tile loads: 128 rows x 128 bf16 = 2048 uint4 per tile.
    for (int q = tid; q < (TILE * D) / 8; q += 256) {
        int r = q >> 4;
        int c = q & 15;
        ((uint4*)(As + r * LDT))[c] =
            ((const uint4*)(Eb + (size_t)(row0 + r) * D))[c];
        ((uint4*)(Bs + r * LDT))[c] =
            ((const uint4*)(Eb + (size_t)(col0 + r) * D))[c];
    }
    __syncthreads();

    const int warp = tid >> 5;
    const int lane = tid & 31;
    const int g = lane >> 2;
    const int tig = lane & 3;
    const int w16 = warp * 16;

    float acc[16][4];
    #pragma unroll
    for (int t = 0; t < 16; t++)
        #pragma unroll
        for (int q = 0; q < 4; q++) acc[t][q] = 0.0f;

    const __nv_bfloat16* Ar = As + (w16 + g) * LDT + 2 * tig;
    const __nv_bfloat16* Br = Bs + g * LDT + 2 * tig;

    #pragma unroll
    for (int kk = 0; kk < 8; kk++) {
        const int kb = kk * 16;
        unsigned a0 = *(const unsigned*)(Ar + kb);
        unsigned a1 = *(const unsigned*)(Ar + 8 * LDT + kb);
        unsigned a2 = *(const unsigned*)(Ar + kb + 8);
        unsigned a3 = *(const unsigned*)(Ar + 8 * LDT + kb + 8);
        #pragma unroll
        for (int t = 0; t < 16; t++) {
            unsigned b0 = *(const unsigned*)(Br + t * 8 * LDT + kb);
            unsigned b1 = *(const unsigned*)(Br + t * 8 * LDT + kb + 8);
            asm volatile(
                "mma.sync.aligned.m16n8k16.row.col.f32.bf16.bf16.f32 "
                "{%0,%1,%2,%3}, {%4,%5,%6,%7}, {%8,%9}, {%0,%1,%2,%3};"
                : "+f"(acc[t][0]), "+f"(acc[t][1]),
                  "+f"(acc[t][2]), "+f"(acc[t][3])
                : "r"(a0), "r"(a1), "r"(a2), "r"(a3), "r"(b0), "r"(b1));
        }
    }

    // ----------------- Register-resident epilogue -----------------
    const int r0l = w16 + g;          // local row of c0/c1
    const int r1l = r0l + 8;          // local row of c2/c3
    const int rt0 = srt[r0l];
    const int rt1 = srt[r1l];
    const int giR0 = subset * M + row0 + r0l;
    const int giR1 = giR0 + 8;
    const int gcBase = subset * M + col0;
    float rm0 = -1e30f, rm1 = -1e30f;

    #pragma unroll
    for (int t = 0; t < 16; t++) {
        const int cA = t * 8 + 2 * tig;
        const int cB = cA + 1;
        const int ctA = sct[cA];
        const int ctB = sct[cB];
        float cm0 = -1e30f, cm1 = -1e30f;
        float s;

        s = acc[t][0];   // (r0, cA)
        if (ctA == rt0) {
            if (!(dg && cA == r0l)) { push_pos(giR0, s); if (!dg) push_pos(gcBase + cA, s); }
        } else {
            rm0 = fmaxf(rm0, s); cm0 = fmaxf(cm0, s);
            if (s > 0.49f) { push_neg(giR0, s); if (!dg) push_neg(gcBase + cA, s); }
        }
        s = acc[t][1];   // (r0, cB)
        if (ctB == rt0) {
            if (!(dg && cB == r0l)) { push_pos(giR0, s); if (!dg) push_pos(gcBase + cB, s); }
        } else {
            rm0 = fmaxf(rm0, s); cm1 = fmaxf(cm1, s);
            if (s > 0.49f) { push_neg(giR0, s); if (!dg) push_neg(gcBase + cB, s); }
        }
        s = acc[t][2];   // (r1, cA)
        if (ctA == rt1) {
            if (!(dg && cA == r1l)) { push_pos(giR1, s); if (!dg) push_pos(gcBase + cA, s); }
        } else {
            rm1 = fmaxf(rm1, s); cm0 = fmaxf(cm0, s);
            if (s > 0.49f) { push_neg(giR1, s); if (!dg) push_neg(gcBase + cA, s); }
        }
        s = acc[t][3];   // (r1, cB)
        if (ctB == rt1) {
            if (!(dg && cB == r1l)) { push_pos(giR1, s); if (!dg) push_pos(gcBase + cB, s); }
        } else {
            rm1 = fmaxf(rm1, s); cm1 = fmaxf(cm1, s);
            if (s > 0.49f) { push_neg(giR1, s); if (!dg) push_neg(gcBase + cB, s); }
        }

        if (!dg) {
            // reduce col maxima over the 8 g-groups (lane bits 2,3,4)
            #pragma unroll
            for (int o = 4; o <= 16; o <<= 1) {
                cm0 = fmaxf(cm0, __shfl_xor_sync(0xffffffffu, cm0, o));
                cm1 = fmaxf(cm1, __shfl_xor_sync(0xffffffffu, cm1, o));
            }
            if (g == 0) {
                if (cm0 > -1e29f) atomicMax(&colE[cA], encf(cm0));
                if (cm1 > -1e29f) atomicMax(&colE[cB], encf(cm1));
            }
        }
    }

    // row maxima: reduce over tig (lane bits 0,1)
    #pragma unroll
    for (int o = 1; o <= 2; o <<= 1) {
        rm0 = fmaxf(rm0, __shfl_xor_sync(0xffffffffu, rm0, o));
        rm1 = fmaxf(rm1, __shfl_xor_sync(0xffffffffu, rm1, o));
    }
    if (tig == 0) {
        if (rm0 > -1e29f) atomicMax(&g_mnE[giR0], encf(rm0));
        if (rm1 > -1e29f) atomicMax(&g_mnE[giR1], encf(rm1));
    }

    if (!dg) {
        __syncthreads();
        if (tid < TILE) {
            unsigned e = colE[tid];
            if (e != encf(-1e30f)) atomicMax(&g_mnE[gcBase + tid], e);
        }
    }
}

// ---------------------------------------------------------------------------
// Row loss, warp-per-row: single pass over the positive list computes
// max_pos AND the pos sum (thrp only needs global max_neg). Stores thrn.
// ---------------------------------------------------------------------------
__global__ __launch_bounds__(256) void rowloss_kernel() {
    __shared__ float wsum[8];
    const int warp = threadIdx.x >> 5;
    const int lane = threadIdx.x & 31;
    const int row = blockIdx.x * 8 + warp;

    const int cnt = min(g_pcnt[row], POS_CAP);
    const float mn = decf(g_mnE[row]);
    const float thrp = mn + 0.1f;
    const float* lst = g_pos + (size_t)row * POS_CAP;

    float loss = 0.0f, mp = -1e30f;
    for (int k = lane; k < cnt; k += 32) {
        float s = lst[k];
        mp = fmaxf(mp, s);
        if (s < thrp) loss += 1.0f - s;
    }
    #pragma unroll
    for (int o = 16; o > 0; o >>= 1) {
        mp = fmaxf(mp, __shfl_xor_sync(0xffffffffu, mp, o));
        loss += __shfl_xor_sync(0xffffffffu, loss, o);
    }
    if (lane == 0) {
        g_thrn[row] = (cnt > 0) ? (fmaxf(0.6f, mp) - 0.1f) : 3e38f;
        wsum[warp] = (cnt > 0) ? loss : 0.0f;
    }
    __syncthreads();
    if (threadIdx.x == 0) {
        float t = 0.0f;
        #pragma unroll
        for (int i = 0; i < 8; i++) t += wsum[i];
        if (t != 0.0f) atomicAdd(&g_acc, t);
    }
}

// ---------------------------------------------------------------------------
// Neg spill: filter recorded negatives (> 0.49) against the real thresholds.
// ---------------------------------------------------------------------------
__global__ __launch_bounds__(256) void negloss_kernel() {
    __shared__ float red[256];
    int n = min(g_ncnt, NEG_CAP);
    float loss = 0.0f;
    for (int k = threadIdx.x; k < n; k += 256) {
        int row = g_negrow[k];
        float s = g_negval[k];
        if (s > g_thrn[row]) loss += s;
    }
    red[threadIdx.x] = loss;
    __syncthreads();
    #pragma unroll
    for (int o = 128; o > 0; o >>= 1) {
        if (threadIdx.x < o) red[threadIdx.x] += red[threadIdx.x + o];
        __syncthreads();
    }
    if (threadIdx.x == 0 && red[0] != 0.0f) atomicAdd(&g_acc, red[0]);
}

// ---------------------------------------------------------------------------
// Finalize: mean over all rows (equal subset sizes -> total / 12288)
// ---------------------------------------------------------------------------
__global__ void fin_kernel(float* out) {
    out[0] = g_acc / (float)BTOT;
}

extern "C" void kernel_launch(void* const* d_in, const int* in_sizes, int n_in,
                              void* d_out, int out_size) {
    const float* emb = (const float*)d_in[0];
    const int* tgt32 = (const int*)d_in[1];
    float* out = (float*)d_out;

    const int smem_bytes = 2 * TILE * LDT * (int)sizeof(__nv_bfloat16); // 69632
    cudaFuncSetAttribute(simpass_kernel,
                         cudaFuncAttributeMaxDynamicSharedMemorySize, smem_bytes);

    detect_kernel<<<1, 1>>>(tgt32);

    prep_kernel<<<(BTOT * D / 4 + 255) / 256, 256>>>(emb, tgt32);

    dim3 tgrid(NTRI, 1, NSUB); // 528 x 1 x 3
    simpass_kernel<<<tgrid, 256, smem_bytes>>>();

    rowloss_kernel<<<BTOT / 8, 256>>>();   // 1536 blocks, warp per row

    negloss_kernel<<<1, 256>>>();

    fin_kernel<<<1, 1>>>(out);
}

// round 15
// speedup vs baseline: 1.2190x; 1.2190x over previous
#include <cuda_runtime.h>
#include <cuda_bf16.h>
#include <cstdint>

// Problem constants
#define NSUB 3
#define M 4096
#define D 128
#define BTOT (NSUB*M)
#define TILE 128
#define NT (M/TILE)            // 32 block-rows per subset
#define NTRI (NT*(NT+1)/2)     // 528 upper-triangle tiles per subset
#define LDT 136                // bf16 smem tile leading dim (272B rows)
#define POS_CAP 128
#define NEG_CAP (1<<20)

// Scratch (device globals -- no allocations allowed)
__device__ __nv_bfloat16 g_embB[BTOT * D];
__device__ int           g_tg[BTOT];
__device__ unsigned      g_mnE[BTOT];            // encoded row max_neg
__device__ int           g_pcnt[BTOT];           // positives count per row
__device__ float         g_pos[(size_t)BTOT * POS_CAP];
__device__ int           g_ncnt;                 // spill count
__device__ int           g_negrow[NEG_CAP];
__device__ float         g_negval[NEG_CAP];
__device__ float         g_thrn[BTOT];
__device__ float         g_acc;
__device__ int           g_tmode;                // 0 = int32 targets, 1 = int64

// Monotone float <-> unsigned encoding (for atomicMax on float)
__device__ __forceinline__ unsigned encf(float f) {
    unsigned u = __float_as_uint(f);
    return (u & 0x80000000u) ? ~u : (u | 0x80000000u);
}
__device__ __forceinline__ float decf(unsigned e) {
    unsigned u = (e & 0x80000000u) ? (e & 0x7fffffffu) : ~e;
    return __uint_as_float(u);
}
__device__ __forceinline__ void push_pos(int row, float s) {
    int k = atomicAdd(&g_pcnt[row], 1);
    if (k < POS_CAP) g_pos[(size_t)row * POS_CAP + k] = s;
}
__device__ __forceinline__ void push_neg(int row, float s) {
    int k = atomicAdd(&g_ncnt, 1);
    if (k < NEG_CAP) { g_negrow[k] = row; g_negval[k] = s; }
}

__device__ __forceinline__ uint32_t smem_u32(const void* p) {
    uint32_t a;
    asm("{ .reg .u64 t; cvta.to.shared.u64 t, %1; cvt.u32.u64 %0, t; }"
        : "=r"(a) : "l"(p));
    return a;
}

// ---------------------------------------------------------------------------
// Detect target dtype layout (targets in [0,512): int64 layout => odd words 0)
// ---------------------------------------------------------------------------
__global__ void detect_kernel(const int* __restrict__ tgt32) {
    int odd_or = 0;
    #pragma unroll
    for (int k = 0; k < 64; k++) odd_or |= tgt32[2 * k + 1];
    g_tmode = (odd_or == 0) ? 1 : 0;
    g_acc = 0.0f;
    g_ncnt = 0;
}

// ---------------------------------------------------------------------------
// Prep: fp32 -> bf16 (vectorized, linear layout), targets -> int32
// ---------------------------------------------------------------------------
__global__ void prep_kernel(const float* __restrict__ emb,
                            const int* __restrict__ tgt32) {
    int idx = blockIdx.x * 256 + threadIdx.x;
    if (idx < BTOT * D / 4) {
        float4 v = reinterpret_cast<const float4*>(emb)[idx];
        __nv_bfloat162 a = __float22bfloat162_rn(make_float2(v.x, v.y));
        __nv_bfloat162 b = __float22bfloat162_rn(make_float2(v.z, v.w));
        uint2 pk;
        pk.x = *reinterpret_cast<unsigned*>(&a);
        pk.y = *reinterpret_cast<unsigned*>(&b);
        reinterpret_cast<uint2*>(g_embB)[idx] = pk;
    }
    if (idx < BTOT) {
        g_tg[idx] = g_tmode ? tgt32[2 * idx] : tgt32[idx];
        g_mnE[idx] = encf(-1e30f);
        g_pcnt[idx] = 0;
    }
}

// ---------------------------------------------------------------------------
// Triangular GEMM pass: ldmatrix + mma.sync.m16n8k16, register epilogue.
// 256 threads = 8 warps; warp (wr,wc) owns a 32x64 subtile: 2 m16-tiles x
// 8 n8-tiles. Fragment layout (PTX-documented, verified correct in R13):
//   lane = 4*g + tig
//   A: a0=(g,2tig{+1}) a1=(g+8,..) a2=(g,2tig+8..) a3=(g+8,2tig+8..)
//   B: b0=B[k=2tig{+1}][n=g]  b1=B[k=2tig+8{+1}][n=g]
//   C: c0,c1=(g,2tig{+1})  c2,c3=(g+8,2tig{+1})
// ldmatrix m8n8 gives lane l elements (row l>>2, colpair l&3) => exact match.
// Epilogue: each acc element classified once in registers. Row max_neg:
// shfl over tig (2) + 1 atomicMax per row. Col max_neg (off-diag): per n8
// pair shfl over g (3 each) + smem atomicMax staging, one flush per tile.
// ---------------------------------------------------------------------------
__global__ __launch_bounds__(256, 2) void simpass_kernel() {
    extern __shared__ __nv_bfloat16 smem[];
    __nv_bfloat16* As = smem;                   // [128][LDT]
    __nv_bfloat16* Bs = smem + TILE * LDT;      // [128][LDT]

    __shared__ int srt[TILE];        // targets of br rows
    __shared__ int sct[TILE];        // targets of bc rows
    __shared__ unsigned colE[TILE];  // encoded col maxima (off-diag)

    const int subset = blockIdx.z;
    const int tid = threadIdx.x;

    // Decode upper-triangle tile index -> (br, bc)
    int rem = blockIdx.x, br = 0;
    while (rem >= NT - br) { rem -= NT - br; br++; }
    const int bc = br + rem;
    const int row0 = br * TILE;
    const int col0 = bc * TILE;
    const bool dg = (br == bc);

    const __nv_bfloat16* Eb = g_embB + (size_t)subset * M * D;

    if (tid < TILE) {
        srt[tid] = g_tg[subset * M + row0 + tid];
        colE[tid] = encf(-1e30f);
    } else {
        sct[tid - TILE] = g_tg[subset * M + col0 + (tid - TILE)];
    }

    // Cooperative tile loads: 128 rows x 128 bf16 = 2048 uint4 per tile.
    for (int q = tid; q < (TILE * D) / 8; q += 256) {
        int r = q >> 4;
        int c = q & 15;
        ((uint4*)(As + r * LDT))[c] =
            ((const uint4*)(Eb + (size_t)(row0 + r) * D))[c];
        ((uint4*)(Bs + r * LDT))[c] =
            ((const uint4*)(Eb + (size_t)(col0 + r) * D))[c];
    }
    __syncthreads();

    const int warp = tid >> 5;
    const int lane = tid & 31;
    const int g = lane >> 2;
    const int tig = lane & 3;
    const int wr = warp >> 1;       // 0..3: 32-row band
    const int wc = warp & 1;        // 0..1: 64-col band

    // ldmatrix per-thread source addresses
    const int lq = lane >> 3;       // 0..3
    const int lr = lane & 7;
    // A x4: q0: rows+0 k0-7 | q1: rows+8 k0-7 | q2: rows+0 k8-15 | q3: rows+8 k8-15
    const uint32_t aAddr = smem_u32(As) +
        (uint32_t)(((wr * 32 + ((lq & 1) << 3) + lr) * LDT + ((lq >> 1) << 3)) * 2);
    // B x2: q0: n-rows k0-7 | q1: n-rows k8-15
    const uint32_t bAddr = smem_u32(Bs) +
        (uint32_t)(((wc * 64 + lr) * LDT + ((lq & 1) << 3)) * 2);

    float acc[2][8][4];
    #pragma unroll
    for (int mi = 0; mi < 2; mi++)
        #pragma unroll
        for (int ni = 0; ni < 8; ni++)
            #pragma unroll
            for (int q = 0; q < 4; q++) acc[mi][ni][q] = 0.0f;

    #pragma unroll
    for (int k = 0; k < 8; k++) {
        const uint32_t kb = k * 32;   // 16 bf16 = 32 bytes per k-step
        uint32_t a[2][4];
        #pragma unroll
        for (int mi = 0; mi < 2; mi++) {
            asm volatile(
                "ldmatrix.sync.aligned.m8n8.x4.shared.b16 {%0,%1,%2,%3}, [%4];"
                : "=r"(a[mi][0]), "=r"(a[mi][1]), "=r"(a[mi][2]), "=r"(a[mi][3])
                : "r"(aAddr + mi * (16 * LDT * 2) + kb));
        }
        #pragma unroll
        for (int ni = 0; ni < 8; ni++) {
            uint32_t b0, b1;
            asm volatile(
                "ldmatrix.sync.aligned.m8n8.x2.shared.b16 {%0,%1}, [%2];"
                : "=r"(b0), "=r"(b1)
                : "r"(bAddr + ni * (8 * LDT * 2) + kb));
            #pragma unroll
            for (int mi = 0; mi < 2; mi++) {
                asm volatile(
                    "mma.sync.aligned.m16n8k16.row.col.f32.bf16.bf16.f32 "
                    "{%0,%1,%2,%3}, {%4,%5,%6,%7}, {%8,%9}, {%0,%1,%2,%3};"
                    : "+f"(acc[mi][ni][0]), "+f"(acc[mi][ni][1]),
                      "+f"(acc[mi][ni][2]), "+f"(acc[mi][ni][3])
                    : "r"(a[mi][0]), "r"(a[mi][1]), "r"(a[mi][2]), "r"(a[mi][3]),
                      "r"(b0), "r"(b1));
            }
        }
    }

    // ----------------- Register epilogue -----------------
    int rt[4], giR[4], rloc[4];
    #pragma unroll
    for (int mi = 0; mi < 2; mi++)
        #pragma unroll
        for (int h = 0; h < 2; h++) {
            int rl = wr * 32 + mi * 16 + h * 8 + g;
            rloc[mi * 2 + h] = rl;
            rt[mi * 2 + h] = srt[rl];
            giR[mi * 2 + h] = subset * M + row0 + rl;
        }
    const int gcBase = subset * M + col0;
    float rmax[4] = { -1e30f, -1e30f, -1e30f, -1e30f };

    #pragma unroll
    for (int ni = 0; ni < 8; ni++) {
        const int cl0 = wc * 64 + ni * 8 + 2 * tig;
        const int cl1 = cl0 + 1;
        const int ct0 = sct[cl0];
        const int ct1 = sct[cl1];
        float cm0 = -1e30f, cm1 = -1e30f;

        #pragma unroll
        for (int mi = 0; mi < 2; mi++)
            #pragma unroll
            for (int h = 0; h < 2; h++) {
                const int rix = mi * 2 + h;
                const int myrt = rt[rix];
                float s0 = acc[mi][ni][h * 2];
                float s1 = acc[mi][ni][h * 2 + 1];

                if (ct0 == myrt) {
                    if (!(dg && cl0 == rloc[rix])) {
                        push_pos(giR[rix], s0);
                        if (!dg) push_pos(gcBase + cl0, s0);
                    }
                } else {
                    rmax[rix] = fmaxf(rmax[rix], s0);
                    cm0 = fmaxf(cm0, s0);
                    if (s0 > 0.49f) {
                        push_neg(giR[rix], s0);
                        if (!dg) push_neg(gcBase + cl0, s0);
                    }
                }
                if (ct1 == myrt) {
                    if (!(dg && cl1 == rloc[rix])) {
                        push_pos(giR[rix], s1);
                        if (!dg) push_pos(gcBase + cl1, s1);
                    }
                } else {
                    rmax[rix] = fmaxf(rmax[rix], s1);
                    cm1 = fmaxf(cm1, s1);
                    if (s1 > 0.49f) {
                        push_neg(giR[rix], s1);
                        if (!dg) push_neg(gcBase + cl1, s1);
                    }
                }
            }

        if (!dg) {
            // reduce col partial maxima over g (lane bits 2,3,4)
            #pragma unroll
            for (int o = 4; o <= 16; o <<= 1) {
                cm0 = fmaxf(cm0, __shfl_xor_sync(0xffffffffu, cm0, o));
                cm1 = fmaxf(cm1, __shfl_xor_sync(0xffffffffu, cm1, o));
            }
            if (g == 0) {
                if (cm0 > -1e29f) atomicMax(&colE[cl0], encf(cm0));
                if (cm1 > -1e29f) atomicMax(&colE[cl1], encf(cm1));
            }
        }
    }

    // row maxima: reduce over tig (lane bits 0,1), one global atomic per row
    #pragma unroll
    for (int rix = 0; rix < 4; rix++) {
        float v = rmax[rix];
        v = fmaxf(v, __shfl_xor_sync(0xffffffffu, v, 1));
        v = fmaxf(v, __shfl_xor_sync(0xffffffffu, v, 2));
        if (tig == 0 && v > -1e29f) atomicMax(&g_mnE[giR[rix]], encf(v));
    }

    if (!dg) {
        __syncthreads();
        if (tid < TILE) {
            unsigned e = colE[tid];
            if (e != encf(-1e30f)) atomicMax(&g_mnE[gcBase + tid], e);
        }
    }
}

// ---------------------------------------------------------------------------
// Row loss, warp-per-row: one pass over the positive list -> max_pos + pos sum.
// ---------------------------------------------------------------------------
__global__ __launch_bounds__(256) void rowloss_kernel() {
    __shared__ float wsum[8];
    const int warp = threadIdx.x >> 5;
    const int lane = threadIdx.x & 31;
    const int row = blockIdx.x * 8 + warp;

    const int cnt = min(g_pcnt[row], POS_CAP);
    const float mn = decf(g_mnE[row]);
    const float thrp = mn + 0.1f;
    const float* lst = g_pos + (size_t)row * POS_CAP;

    float loss = 0.0f, mp = -1e30f;
    for (int k = lane; k < cnt; k += 32) {
        float s = lst[k];
        mp = fmaxf(mp, s);
        if (s < thrp) loss += 1.0f - s;
    }
    #pragma unroll
    for (int o = 16; o > 0; o >>= 1) {
        mp = fmaxf(mp, __shfl_xor_sync(0xffffffffu, mp, o));
        loss += __shfl_xor_sync(0xffffffffu, loss, o);
    }
    if (lane == 0) {
        g_thrn[row] = (cnt > 0) ? (fmaxf(0.6f, mp) - 0.1f) : 3e38f;
        wsum[warp] = (cnt > 0) ? loss : 0.0f;
    }
    __syncthreads();
    if (threadIdx.x == 0) {
        float t = 0.0f;
        #pragma unroll
        for (int i = 0; i < 8; i++) t += wsum[i];
        if (t != 0.0f) atomicAdd(&g_acc, t);
    }
}

// ---------------------------------------------------------------------------
// Neg spill: filter recorded negatives (> 0.49) against the real thresholds.
// ---------------------------------------------------------------------------
__global__ __launch_bounds__(256) void negloss_kernel() {
    __shared__ float red[256];
    int n = min(g_ncnt, NEG_CAP);
    float loss = 0.0f;
    for (int k = threadIdx.x; k < n; k += 256) {
        int row = g_negrow[k];
        float s = g_negval[k];
        if (s > g_thrn[row]) loss += s;
    }
    red[threadIdx.x] = loss;
    __syncthreads();
    #pragma unroll
    for (int o = 128; o > 0; o >>= 1) {
        if (threadIdx.x < o) red[threadIdx.x] += red[threadIdx.x + o];
        __syncthreads();
    }
    if (threadIdx.x == 0 && red[0] != 0.0f) atomicAdd(&g_acc, red[0]);
}

__global__ void fin_kernel(float* out) {
    out[0] = g_acc / (float)BTOT;
}

extern "C" void kernel_launch(void* const* d_in, const int* in_sizes, int n_in,
                              void* d_out, int out_size) {
    const float* emb = (const float*)d_in[0];
    const int* tgt32 = (const int*)d_in[1];
    float* out = (float*)d_out;

    const int smem_bytes = 2 * TILE * LDT * (int)sizeof(__nv_bfloat16); // 69632
    cudaFuncSetAttribute(simpass_kernel,
                         cudaFuncAttributeMaxDynamicSharedMemorySize, smem_bytes);

    detect_kernel<<<1, 1>>>(tgt32);

    prep_kernel<<<(BTOT * D / 4 + 255) / 256, 256>>>(emb, tgt32);

    dim3 tgrid(NTRI, 1, NSUB); // 528 x 1 x 3
    simpass_kernel<<<tgrid, 256, smem_bytes>>>();

    rowloss_kernel<<<BTOT / 8, 256>>>();

    negloss_kernel<<<1, 256>>>();

    fin_kernel<<<1, 1>>>(out);
}

// round 16
// speedup vs baseline: 1.6958x; 1.3912x over previous
#include <cuda_runtime.h>
#include <cuda_bf16.h>
#include <cstdint>

// Problem constants
#define NSUB 3
#define M 4096
#define D 128
#define BTOT (NSUB*M)
#define TILE 128
#define NT (M/TILE)            // 32 block-rows per subset
#define NTRI (NT*(NT+1)/2)     // 528 upper-triangle tiles per subset
#define LDT 136                // bf16 smem tile leading dim (272B rows)
#define POS_CAP 128
#define NEG_CAP (1<<20)
#define NCLS 512               // targets in [0, 512)

// Scratch (device globals -- no allocations allowed)
__device__ __nv_bfloat16 g_embB[BTOT * D];   // row-sorted-by-target embeddings
__device__ int           g_tg[BTOT];         // sorted targets
__device__ int           g_cursor[NSUB * NCLS];
__device__ int           g_perm[BTOT];       // src row -> sorted position
__device__ unsigned      g_mnE[BTOT];        // encoded row max_neg
__device__ int           g_pcnt[BTOT];       // positives count per row
__device__ float         g_pos[(size_t)BTOT * POS_CAP];
__device__ int           g_ncnt;             // spill count
__device__ int           g_negrow[NEG_CAP];
__device__ float         g_negval[NEG_CAP];
__device__ float         g_thrn[BTOT];
__device__ float         g_acc;
__device__ int           g_tmode;            // 0 = int32 targets, 1 = int64

// Monotone float <-> unsigned encoding (for atomicMax on float)
__device__ __forceinline__ unsigned encf(float f) {
    unsigned u = __float_as_uint(f);
    return (u & 0x80000000u) ? ~u : (u | 0x80000000u);
}
__device__ __forceinline__ float decf(unsigned e) {
    unsigned u = (e & 0x80000000u) ? (e & 0x7fffffffu) : ~e;
    return __uint_as_float(u);
}
__device__ __forceinline__ void push_pos(int row, float s) {
    int k = atomicAdd(&g_pcnt[row], 1);
    if (k < POS_CAP) g_pos[(size_t)row * POS_CAP + k] = s;
}
__device__ __forceinline__ void push_neg(int row, float s) {
    int k = atomicAdd(&g_ncnt, 1);
    if (k < NEG_CAP) { g_negrow[k] = row; g_negval[k] = s; }
}
__device__ __forceinline__ uint32_t smem_u32(const void* p) {
    uint32_t a;
    asm("{ .reg .u64 t; cvta.to.shared.u64 t, %1; cvt.u32.u64 %0, t; }"
        : "=r"(a) : "l"(p));
    return a;
}

// ---------------------------------------------------------------------------
// Detect target dtype layout (targets in [0,512): int64 layout => odd words 0)
// ---------------------------------------------------------------------------
__global__ void detect_kernel(const int* __restrict__ tgt32) {
    int odd_or = 0;
    #pragma unroll
    for (int k = 0; k < 64; k++) odd_or |= tgt32[2 * k + 1];
    g_tmode = (odd_or == 0) ? 1 : 0;
    g_acc = 0.0f;
    g_ncnt = 0;
}

// ---------------------------------------------------------------------------
// Counting-sort step 1: per-subset target histogram + exclusive scan -> cursor
// ---------------------------------------------------------------------------
__global__ __launch_bounds__(NCLS) void hist_kernel(const int* __restrict__ tgt32) {
    __shared__ int bins[NCLS];
    const int tid = threadIdx.x;
    const int sub = blockIdx.x;
    bins[tid] = 0;
    __syncthreads();
    for (int r = tid; r < M; r += NCLS) {
        int gi = sub * M + r;
        int t = g_tmode ? tgt32[2 * gi] : tgt32[gi];
        atomicAdd(&bins[t], 1);
    }
    __syncthreads();
    int own = bins[tid];
    // Hillis-Steele inclusive scan
    for (int off = 1; off < NCLS; off <<= 1) {
        int v = (tid >= off) ? bins[tid - off] : 0;
        __syncthreads();
        bins[tid] += v;
        __syncthreads();
    }
    g_cursor[sub * NCLS + tid] = bins[tid] - own;  // exclusive prefix
}

// ---------------------------------------------------------------------------
// Counting-sort step 2: scatter. perm[src] = sorted position; sorted targets.
// Also resets per-row state.
// ---------------------------------------------------------------------------
__global__ void scatter_kernel(const int* __restrict__ tgt32) {
    int idx = blockIdx.x * 256 + threadIdx.x;
    if (idx >= BTOT) return;
    int sub = idx >> 12;
    int t = g_tmode ? tgt32[2 * idx] : tgt32[idx];
    int p = atomicAdd(&g_cursor[sub * NCLS + t], 1);
    g_perm[idx] = p;
    g_tg[sub * M + p] = t;
    g_mnE[idx] = encf(-1e30f);
    g_pcnt[idx] = 0;
}

// ---------------------------------------------------------------------------
// Prep gather: fp32 -> bf16 into the sorted row order.
// Thread handles one float4 (4 cols) of one source row.
// ---------------------------------------------------------------------------
__global__ void prep_kernel(const float* __restrict__ emb) {
    int idx = blockIdx.x * 256 + threadIdx.x;
    if (idx >= BTOT * (D / 4)) return;
    int srcRow = idx >> 5;          // D/4 = 32 float4 per row
    int j = idx & 31;
    int sub = srcRow >> 12;
    int p = g_perm[srcRow];

    float4 v = reinterpret_cast<const float4*>(emb)[idx];
    __nv_bfloat162 a = __float22bfloat162_rn(make_float2(v.x, v.y));
    __nv_bfloat162 b = __float22bfloat162_rn(make_float2(v.z, v.w));
    uint2 pk;
    pk.x = *reinterpret_cast<unsigned*>(&a);
    pk.y = *reinterpret_cast<unsigned*>(&b);
    reinterpret_cast<uint2*>(g_embB)[(size_t)(sub * M + p) * 32 + j] = pk;
}

// ---------------------------------------------------------------------------
// Triangular GEMM pass: ldmatrix + mma.sync.m16n8k16, register epilogue.
// Rows sorted by target => off-diag tile (br<bc) contains positives iff
// tg[row0+127] == tg[col0] (class straddles both blocks). ~88% of tiles are
// pure-negative: epilogue = 2 FMNMX/element, no compares, warp-vote spill.
// ---------------------------------------------------------------------------
__global__ __launch_bounds__(256, 2) void simpass_kernel() {
    extern __shared__ __nv_bfloat16 smem[];
    __nv_bfloat16* As = smem;                   // [128][LDT]
    __nv_bfloat16* Bs = smem + TILE * LDT;      // [128][LDT]

    __shared__ int srt[TILE];        // targets of br rows
    __shared__ int sct[TILE];        // targets of bc rows
    __shared__ unsigned colE[TILE];  // encoded col maxima (off-diag)

    const int subset = blockIdx.z;
    const int tid = threadIdx.x;

    // Decode upper-triangle tile index -> (br, bc)
    int rem = blockIdx.x, br = 0;
    while (rem >= NT - br) { rem -= NT - br; br++; }
    const int bc = br + rem;
    const int row0 = br * TILE;
    const int col0 = bc * TILE;
    const bool dg = (br == bc);

    const __nv_bfloat16* Eb = g_embB + (size_t)subset * M * D;

    if (tid < TILE) {
        srt[tid] = g_tg[subset * M + row0 + tid];
        colE[tid] = encf(-1e30f);
    } else {
        sct[tid - TILE] = g_tg[subset * M + col0 + (tid - TILE)];
    }

    // Cooperative tile loads: 128 rows x 128 bf16 = 2048 uint4 per tile.
    for (int q = tid; q < (TILE * D) / 8; q += 256) {
        int r = q >> 4;
        int c = q & 15;
        ((uint4*)(As + r * LDT))[c] =
            ((const uint4*)(Eb + (size_t)(row0 + r) * D))[c];
        ((uint4*)(Bs + r * LDT))[c] =
            ((const uint4*)(Eb + (size_t)(col0 + r) * D))[c];
    }
    __syncthreads();

    const bool mixed = dg || (srt[TILE - 1] == sct[0]);

    const int warp = tid >> 5;
    const int lane = tid & 31;
    const int g = lane >> 2;
    const int tig = lane & 3;
    const int wr = warp >> 1;       // 0..3: 32-row band
    const int wc = warp & 1;        // 0..1: 64-col band

    // ldmatrix per-thread source addresses
    const int lq = lane >> 3;       // 0..3
    const int lr = lane & 7;
    const uint32_t aAddr = smem_u32(As) +
        (uint32_t)(((wr * 32 + ((lq & 1) << 3) + lr) * LDT + ((lq >> 1) << 3)) * 2);
    const uint32_t bAddr = smem_u32(Bs) +
        (uint32_t)(((wc * 64 + lr) * LDT + ((lq & 1) << 3)) * 2);

    float acc[2][8][4];
    #pragma unroll
    for (int mi = 0; mi < 2; mi++)
        #pragma unroll
        for (int ni = 0; ni < 8; ni++)
            #pragma unroll
            for (int q = 0; q < 4; q++) acc[mi][ni][q] = 0.0f;

    #pragma unroll
    for (int k = 0; k < 8; k++) {
        const uint32_t kb = k * 32;   // 16 bf16 = 32 bytes per k-step
        uint32_t a[2][4];
        #pragma unroll
        for (int mi = 0; mi < 2; mi++) {
            asm volatile(
                "ldmatrix.sync.aligned.m8n8.x4.shared.b16 {%0,%1,%2,%3}, [%4];"
                : "=r"(a[mi][0]), "=r"(a[mi][1]), "=r"(a[mi][2]), "=r"(a[mi][3])
                : "r"(aAddr + mi * (16 * LDT * 2) + kb));
        }
        #pragma unroll
        for (int ni = 0; ni < 8; ni++) {
            uint32_t b0, b1;
            asm volatile(
                "ldmatrix.sync.aligned.m8n8.x2.shared.b16 {%0,%1}, [%2];"
                : "=r"(b0), "=r"(b1)
                : "r"(bAddr + ni * (8 * LDT * 2) + kb));
            #pragma unroll
            for (int mi = 0; mi < 2; mi++) {
                asm volatile(
                    "mma.sync.aligned.m16n8k16.row.col.f32.bf16.bf16.f32 "
                    "{%0,%1,%2,%3}, {%4,%5,%6,%7}, {%8,%9}, {%0,%1,%2,%3};"
                    : "+f"(acc[mi][ni][0]), "+f"(acc[mi][ni][1]),
                      "+f"(acc[mi][ni][2]), "+f"(acc[mi][ni][3])
                    : "r"(a[mi][0]), "r"(a[mi][1]), "r"(a[mi][2]), "r"(a[mi][3]),
                      "r"(b0), "r"(b1));
            }
        }
    }

    // ----------------- Epilogue -----------------
    int giR[4], rloc[4];
    #pragma unroll
    for (int mi = 0; mi < 2; mi++)
        #pragma unroll
        for (int h = 0; h < 2; h++) {
            int rl = wr * 32 + mi * 16 + h * 8 + g;
            rloc[mi * 2 + h] = rl;
            giR[mi * 2 + h] = subset * M + row0 + rl;
        }
    const int gcBase = subset * M + col0;
    float rmax[4] = { -1e30f, -1e30f, -1e30f, -1e30f };

    if (!mixed) {
        // ---------- Fast path: all elements are negatives ----------
        #pragma unroll
        for (int ni = 0; ni < 8; ni++) {
            const int cl0 = wc * 64 + ni * 8 + 2 * tig;
            float cm0 = -1e30f, cm1 = -1e30f;
            #pragma unroll
            for (int mi = 0; mi < 2; mi++)
                #pragma unroll
                for (int h = 0; h < 2; h++) {
                    const int rix = mi * 2 + h;
                    float s0 = acc[mi][ni][h * 2];
                    float s1 = acc[mi][ni][h * 2 + 1];
                    rmax[rix] = fmaxf(rmax[rix], fmaxf(s0, s1));
                    cm0 = fmaxf(cm0, s0);
                    cm1 = fmaxf(cm1, s1);
                }
            #pragma unroll
            for (int o = 4; o <= 16; o <<= 1) {
                cm0 = fmaxf(cm0, __shfl_xor_sync(0xffffffffu, cm0, o));
                cm1 = fmaxf(cm1, __shfl_xor_sync(0xffffffffu, cm1, o));
            }
            if (g == 0) {
                atomicMax(&colE[cl0], encf(cm0));
                atomicMax(&colE[cl0 + 1], encf(cm1));
            }
        }
        // Rare spill rescan (p ~ 1e-8 per element)
        float lm = fmaxf(fmaxf(rmax[0], rmax[1]), fmaxf(rmax[2], rmax[3]));
        if (__any_sync(0xffffffffu, lm > 0.49f)) {
            #pragma unroll
            for (int ni = 0; ni < 8; ni++)
                #pragma unroll
                for (int mi = 0; mi < 2; mi++)
                    #pragma unroll
                    for (int h = 0; h < 2; h++) {
                        const int rix = mi * 2 + h;
                        #pragma unroll
                        for (int q = 0; q < 2; q++) {
                            float s = acc[mi][ni][h * 2 + q];
                            if (s > 0.49f) {
                                int cl = wc * 64 + ni * 8 + 2 * tig + q;
                                push_neg(giR[rix], s);
                                push_neg(gcBase + cl, s);
                            }
                        }
                    }
        }
    } else {
        // ---------- Mixed path (diag + class-straddle tiles) ----------
        int rt[4];
        #pragma unroll
        for (int rix = 0; rix < 4; rix++) rt[rix] = srt[rloc[rix]];

        #pragma unroll
        for (int ni = 0; ni < 8; ni++) {
            const int cl0 = wc * 64 + ni * 8 + 2 * tig;
            const int cl1 = cl0 + 1;
            const int ct0 = sct[cl0];
            const int ct1 = sct[cl1];
            float cm0 = -1e30f, cm1 = -1e30f;

            #pragma unroll
            for (int mi = 0; mi < 2; mi++)
                #pragma unroll
                for (int h = 0; h < 2; h++) {
                    const int rix = mi * 2 + h;
                    const int myrt = rt[rix];
                    float s0 = acc[mi][ni][h * 2];
                    float s1 = acc[mi][ni][h * 2 + 1];

                    if (ct0 == myrt) {
                        if (!(dg && cl0 == rloc[rix])) {
                            push_pos(giR[rix], s0);
                            if (!dg) push_pos(gcBase + cl0, s0);
                        }
                    } else {
                        rmax[rix] = fmaxf(rmax[rix], s0);
                        cm0 = fmaxf(cm0, s0);
                        if (s0 > 0.49f) {
                            push_neg(giR[rix], s0);
                            if (!dg) push_neg(gcBase + cl0, s0);
                        }
                    }
                    if (ct1 == myrt) {
                        if (!(dg && cl1 == rloc[rix])) {
                            push_pos(giR[rix], s1);
                            if (!dg) push_pos(gcBase + cl1, s1);
                        }
                    } else {
                        rmax[rix] = fmaxf(rmax[rix], s1);
                        cm1 = fmaxf(cm1, s1);
                        if (s1 > 0.49f) {
                            push_neg(giR[rix], s1);
                            if (!dg) push_neg(gcBase + cl1, s1);
                        }
                    }
                }

            if (!dg) {
                #pragma unroll
                for (int o = 4; o <= 16; o <<= 1) {
                    cm0 = fmaxf(cm0, __shfl_xor_sync(0xffffffffu, cm0, o));
                    cm1 = fmaxf(cm1, __shfl_xor_sync(0xffffffffu, cm1, o));
                }
                if (g == 0) {
                    if (cm0 > -1e29f) atomicMax(&colE[cl0], encf(cm0));
                    if (cm1 > -1e29f) atomicMax(&colE[cl1], encf(cm1));
                }
            }
        }
    }

    // row maxima: reduce over tig (lane bits 0,1), one global atomic per row
    #pragma unroll
    for (int rix = 0; rix < 4; rix++) {
        float v = rmax[rix];
        v = fmaxf(v, __shfl_xor_sync(0xffffffffu, v, 1));
        v = fmaxf(v, __shfl_xor_sync(0xffffffffu, v, 2));
        if (tig == 0 && v > -1e29f) atomicMax(&g_mnE[giR[rix]], encf(v));
    }

    if (!dg) {
        __syncthreads();
        if (tid < TILE) {
            unsigned e = colE[tid];
            if (e != encf(-1e30f)) atomicMax(&g_mnE[gcBase + tid], e);
        }
    }
}

// ---------------------------------------------------------------------------
// Row loss, warp-per-row: one pass over the positive list -> max_pos + pos sum.
// ---------------------------------------------------------------------------
__global__ __launch_bounds__(256) void rowloss_kernel() {
    __shared__ float wsum[8];
    const int warp = threadIdx.x >> 5;
    const int lane = threadIdx.x & 31;
    const int row = blockIdx.x * 8 + warp;

    const int cnt = min(g_pcnt[row], POS_CAP);
    const float mn = decf(g_mnE[row]);
    const float thrp = mn + 0.1f;
    const float* lst = g_pos + (size_t)row * POS_CAP;

    float loss = 0.0f, mp = -1e30f;
    for (int k = lane; k < cnt; k += 32) {
        float s = lst[k];
        mp = fmaxf(mp, s);
        if (s < thrp) loss += 1.0f - s;
    }
    #pragma unroll
    for (int o = 16; o > 0; o >>= 1) {
        mp = fmaxf(mp, __shfl_xor_sync(0xffffffffu, mp, o));
        loss += __shfl_xor_sync(0xffffffffu, loss, o);
    }
    if (lane == 0) {
        g_thrn[row] = (cnt > 0) ? (fmaxf(0.6f, mp) - 0.1f) : 3e38f;
        wsum[warp] = (cnt > 0) ? loss : 0.0f;
    }
    __syncthreads();
    if (threadIdx.x == 0) {
        float t = 0.0f;
        #pragma unroll
        for (int i = 0; i < 8; i++) t += wsum[i];
        if (t != 0.0f) atomicAdd(&g_acc, t);
    }
}

// ---------------------------------------------------------------------------
// Neg spill: filter recorded negatives (> 0.49) against the real thresholds.
// ---------------------------------------------------------------------------
__global__ __launch_bounds__(256) void negloss_kernel() {
    __shared__ float red[256];
    int n = min(g_ncnt, NEG_CAP);
    float loss = 0.0f;
    for (int k = threadIdx.x; k < n; k += 256) {
        int row = g_negrow[k];
        float s = g_negval[k];
        if (s > g_thrn[row]) loss += s;
    }
    red[threadIdx.x] = loss;
    __syncthreads();
    #pragma unroll
    for (int o = 128; o > 0; o >>= 1) {
        if (threadIdx.x < o) red[threadIdx.x] += red[threadIdx.x + o];
        __syncthreads();
    }
    if (threadIdx.x == 0 && red[0] != 0.0f) atomicAdd(&g_acc, red[0]);
}

__global__ void fin_kernel(float* out) {
    out[0] = g_acc / (float)BTOT;
}

extern "C" void kernel_launch(void* const* d_in, const int* in_sizes, int n_in,
                              void* d_out, int out_size) {
    const float* emb = (const float*)d_in[0];
    const int* tgt32 = (const int*)d_in[1];
    float* out = (float*)d_out;

    const int smem_bytes = 2 * TILE * LDT * (int)sizeof(__nv_bfloat16); // 69632
    cudaFuncSetAttribute(simpass_kernel,
                         cudaFuncAttributeMaxDynamicSharedMemorySize, smem_bytes);

    detect_kernel<<<1, 1>>>(tgt32);

    hist_kernel<<<NSUB, NCLS>>>(tgt32);

    scatter_kernel<<<(BTOT + 255) / 256, 256>>>(tgt32);

    prep_kernel<<<(BTOT * (D / 4) + 255) / 256, 256>>>(emb);

    dim3 tgrid(NTRI, 1, NSUB); // 528 x 1 x 3
    simpass_kernel<<<tgrid, 256, smem_bytes>>>();

    rowloss_kernel<<<BTOT / 8, 256>>>();

    negloss_kernel<<<1, 256>>>();

    fin_kernel<<<1, 1>>>(out);
}